// round 2
// baseline (speedup 1.0000x reference)
#include <cuda_runtime.h>
#include <math.h>

#define B_ROWS 8192
#define KNN    32
#define D      512

// 1/sqrt(512)
#define SCORE_SCALE 0.044194173824159220f

// -------- device scratch (allocation-free) --------
__device__ float g_W[D * D];          // w1^T @ w2   [d', d]
__device__ float g_c[D];              // b1 @ w2     [d]
__device__ float g_u[D];              // w1^T @ b2   [d]
__device__ float g_s0;                // b1 . b2
__device__ float g_q2[(size_t)B_ROWS * D];  // x @ W + c

// ---- packed fp32x2 helpers (Blackwell FFMA2) ----
__device__ __forceinline__ void fma2(unsigned long long& d,
                                     unsigned long long a,
                                     unsigned long long b) {
    asm("fma.rn.f32x2 %0, %1, %2, %0;" : "+l"(d) : "l"(a), "l"(b));
}
__device__ __forceinline__ unsigned long long pack_dup(float a) {
    unsigned long long r;
    unsigned int ai = __float_as_uint(a);
    asm("mov.b64 %0, {%1, %1};" : "=l"(r) : "r"(ai));
    return r;
}

// ============================================================
// Kernel 1: W[m,n] = sum_e w1[e,m] * w2[e,n]   (512x512x512)
// 64x64 tiles, BK=16, 256 threads, 4x4 per thread
// ============================================================
__global__ __launch_bounds__(256) void k_prep_W(const float* __restrict__ w1,
                                                const float* __restrict__ w2) {
    __shared__ __align__(16) float As[16][64];
    __shared__ __align__(16) float Bs[16][64];
    const int t  = threadIdx.x;
    const int tx = t & 15;
    const int ty = t >> 4;
    const int m0 = blockIdx.y * 64;
    const int n0 = blockIdx.x * 64;

    const int lr = t >> 4;         // 0..15 (k row within tile)
    const int lc = (t & 15) * 4;   // 0..60 (col4)

    float acc[4][4];
#pragma unroll
    for (int i = 0; i < 4; i++)
#pragma unroll
        for (int j = 0; j < 4; j++) acc[i][j] = 0.f;

    for (int k0 = 0; k0 < D; k0 += 16) {
        float4 a = *(const float4*)(w1 + (size_t)(k0 + lr) * D + m0 + lc);
        float4 b = *(const float4*)(w2 + (size_t)(k0 + lr) * D + n0 + lc);
        *(float4*)&As[lr][lc] = a;
        *(float4*)&Bs[lr][lc] = b;
        __syncthreads();
#pragma unroll
        for (int k = 0; k < 16; k++) {
            float ar[4], br[4];
#pragma unroll
            for (int i = 0; i < 4; i++) ar[i] = As[k][ty * 4 + i];
#pragma unroll
            for (int j = 0; j < 4; j++) br[j] = Bs[k][tx * 4 + j];
#pragma unroll
            for (int i = 0; i < 4; i++)
#pragma unroll
                for (int j = 0; j < 4; j++) acc[i][j] += ar[i] * br[j];
        }
        __syncthreads();
    }
#pragma unroll
    for (int i = 0; i < 4; i++) {
        float4 v = make_float4(acc[i][0], acc[i][1], acc[i][2], acc[i][3]);
        *(float4*)&g_W[(size_t)(m0 + ty * 4 + i) * D + n0 + tx * 4] = v;
    }
}

// ============================================================
// Kernel 2: c[d] = sum_e b1[e]*w2[e,d];  u[d] = sum_e b2[e]*w1[e,d];
//           s0 = b1.b2
// ============================================================
__global__ void k_prep_aux(const float* __restrict__ w1,
                           const float* __restrict__ w2,
                           const float* __restrict__ b1,
                           const float* __restrict__ b2) {
    const int d = blockIdx.x * blockDim.x + threadIdx.x;
    float cacc = 0.f, uacc = 0.f;
#pragma unroll 8
    for (int e = 0; e < D; e++) {
        float b1e = b1[e];
        float b2e = b2[e];
        cacc += b1e * w2[(size_t)e * D + d];
        uacc += b2e * w1[(size_t)e * D + d];
    }
    g_c[d] = cacc;
    g_u[d] = uacc;
    if (blockIdx.x == 0 && threadIdx.x < 32) {
        float s = 0.f;
        for (int e = threadIdx.x; e < D; e += 32) s += b1[e] * b2[e];
#pragma unroll
        for (int o = 16; o; o >>= 1) s += __shfl_xor_sync(0xffffffffu, s, o);
        if (threadIdx.x == 0) g_s0 = s;
    }
}

// ============================================================
// Kernel 3: q2 = x @ W + c     (8192 x 512 x 512 SGEMM)
// BM=128 BN=128 BK=8, 256 threads, 8x8 per thread, FFMA2 (f32x2)
// grid: (N/128=4, M/128=64)
// ============================================================
__global__ __launch_bounds__(256) void k_gemm_q2(const float* __restrict__ X) {
    __shared__ __align__(16) float As[8][128];
    __shared__ __align__(16) float Bs[8][128];
    const int t  = threadIdx.x;
    const int tx = t & 15;   // 0..15 -> col group
    const int ty = t >> 4;   // 0..15 -> row group
    const int bx = blockIdx.x;   // col tile (0..3)
    const int by = blockIdx.y;   // row tile (0..63)

    const int aRow  = t >> 1;          // 0..127
    const int aCol4 = (t & 1) * 4;     // 0 or 4
    const int bRow  = t >> 5;          // 0..7
    const int bCol4 = (t & 31) * 4;    // 0..124

    const float* Aptr = X + ((size_t)by * 128 + aRow) * D + aCol4;
    const float* Bptr = g_W + (size_t)bRow * D + bx * 128 + bCol4;

    // packed accumulators: 8 rows x 4 col-pairs (= 8 cols)
    unsigned long long acc2[8][4];
#pragma unroll
    for (int i = 0; i < 8; i++)
#pragma unroll
        for (int j = 0; j < 4; j++) acc2[i][j] = 0ull;

    // prefetch first tile
    float4 av = *(const float4*)(Aptr);
    float4 bv = *(const float4*)(Bptr);

    for (int k0 = 0; k0 < D; k0 += 8) {
        As[aCol4 + 0][aRow] = av.x;
        As[aCol4 + 1][aRow] = av.y;
        As[aCol4 + 2][aRow] = av.z;
        As[aCol4 + 3][aRow] = av.w;
        *(float4*)&Bs[bRow][bCol4] = bv;
        __syncthreads();

        // prefetch next tile while computing this one
        if (k0 + 8 < D) {
            av = *(const float4*)(Aptr + k0 + 8);
            bv = *(const float4*)(Bptr + (size_t)(k0 + 8) * D);
        }

#pragma unroll
        for (int k = 0; k < 8; k++) {
            float ar[8];
            *(float4*)&ar[0] = *(const float4*)&As[k][ty * 8];
            *(float4*)&ar[4] = *(const float4*)&As[k][ty * 8 + 4];
            // B fragment as two double2 = four f32x2 lane pairs (no pack needed)
            double2 b01 = *(const double2*)&Bs[k][tx * 8];
            double2 b23 = *(const double2*)&Bs[k][tx * 8 + 4];
            unsigned long long br[4];
            br[0] = __double_as_longlong(b01.x);
            br[1] = __double_as_longlong(b01.y);
            br[2] = __double_as_longlong(b23.x);
            br[3] = __double_as_longlong(b23.y);
#pragma unroll
            for (int i = 0; i < 8; i++) {
                unsigned long long ad = pack_dup(ar[i]);
                fma2(acc2[i][0], ad, br[0]);
                fma2(acc2[i][1], ad, br[1]);
                fma2(acc2[i][2], ad, br[2]);
                fma2(acc2[i][3], ad, br[3]);
            }
        }
        __syncthreads();
    }

    // epilogue: unpack, add c, store
    float cfr[8];
#pragma unroll
    for (int j = 0; j < 8; j++) cfr[j] = g_c[bx * 128 + tx * 8 + j];
#pragma unroll
    for (int i = 0; i < 8; i++) {
        float a[8];
#pragma unroll
        for (int j = 0; j < 4; j++) {
            a[2 * j]     = __uint_as_float((unsigned int)(acc2[i][j] & 0xffffffffull));
            a[2 * j + 1] = __uint_as_float((unsigned int)(acc2[i][j] >> 32));
        }
        const size_t row = (size_t)by * 128 + ty * 8 + i;
        float* dst = g_q2 + row * D + bx * 128 + tx * 8;
        float4 v0 = make_float4(a[0] + cfr[0], a[1] + cfr[1],
                                a[2] + cfr[2], a[3] + cfr[3]);
        float4 v1 = make_float4(a[4] + cfr[4], a[5] + cfr[5],
                                a[6] + cfr[6], a[7] + cfr[7]);
        *(float4*)dst       = v0;
        *(float4*)(dst + 4) = v1;
    }
}

// ============================================================
// Kernel 4: per-row attention + blend.
// scores[k] = (q2[b].keys[b,k] + x[b].u + s0) / sqrt(D)
// out = 0.5*x + 0.5*softmax(scores) @ values[b]
// one block (256 threads) per row b
// ============================================================
__global__ __launch_bounds__(256) void k_attention(const float* __restrict__ x,
                                                   const float* __restrict__ keys,
                                                   const float* __restrict__ values,
                                                   float* __restrict__ out) {
    __shared__ __align__(16) float xs[D];
    __shared__ __align__(16) float q2s[D];
    __shared__ float att_s[KNN];
    __shared__ float warp_red[8];
    __shared__ float qb2_sh;

    const int b    = blockIdx.x;
    const int t    = threadIdx.x;
    const int lane = t & 31;
    const int w    = t >> 5;

    // load x row and q2 row to smem (128 float4 each, 256 threads total)
    if (t < 128) {
        ((float4*)xs)[t] = ((const float4*)(x + (size_t)b * D))[t];
    } else {
        ((float4*)q2s)[t - 128] = ((const float4*)(g_q2 + (size_t)b * D))[t - 128];
    }
    __syncthreads();

    // qb2 = x[b] . u + s0
    {
        float p = xs[t] * g_u[t] + xs[t + 256] * g_u[t + 256];
#pragma unroll
        for (int o = 16; o; o >>= 1) p += __shfl_xor_sync(0xffffffffu, p, o);
        if (lane == 0) warp_red[w] = p;
        __syncthreads();
        if (t == 0) {
            float s = 0.f;
#pragma unroll
            for (int i = 0; i < 8; i++) s += warp_red[i];
            qb2_sh = s + g_s0;
        }
        __syncthreads();
    }

    // scores: each warp handles 4 keys
    const float4* q2s4 = (const float4*)q2s;
    const float* kbase = keys + (size_t)b * KNN * D;
#pragma unroll
    for (int kk = 0; kk < 4; kk++) {
        const int k = w * 4 + kk;
        const float4* kr = (const float4*)(kbase + (size_t)k * D);
        float p = 0.f;
#pragma unroll
        for (int i = 0; i < 4; i++) {
            float4 kv = kr[lane + 32 * i];
            float4 qv = q2s4[lane + 32 * i];
            p += kv.x * qv.x + kv.y * qv.y + kv.z * qv.z + kv.w * qv.w;
        }
#pragma unroll
        for (int o = 16; o; o >>= 1) p += __shfl_xor_sync(0xffffffffu, p, o);
        if (lane == 0) att_s[k] = (p + qb2_sh) * SCORE_SCALE;
    }
    __syncthreads();

    // softmax over 32 scores (warp 0)
    if (t < 32) {
        float s = att_s[t];
        float m = s;
#pragma unroll
        for (int o = 16; o; o >>= 1) m = fmaxf(m, __shfl_xor_sync(0xffffffffu, m, o));
        float e = expf(s - m);
        float sum = e;
#pragma unroll
        for (int o = 16; o; o >>= 1) sum += __shfl_xor_sync(0xffffffffu, sum, o);
        att_s[t] = e / sum;
    }
    __syncthreads();

    // combined = att @ values[b]; out = 0.5*x + 0.5*combined
    const float* vbase = values + (size_t)b * KNN * D;
    float ax = 0.f, ay = 0.f;
#pragma unroll 4
    for (int k = 0; k < KNN; k++) {
        float a = att_s[k];
        float2 v = *(const float2*)(vbase + (size_t)k * D + 2 * t);
        ax += a * v.x;
        ay += a * v.y;
    }
    float2 xv = *(const float2*)&xs[2 * t];
    float2 o;
    o.x = 0.5f * xv.x + 0.5f * ax;
    o.y = 0.5f * xv.y + 0.5f * ay;
    *(float2*)(out + (size_t)b * D + 2 * t) = o;
}

// ============================================================
extern "C" void kernel_launch(void* const* d_in, const int* in_sizes, int n_in,
                              void* d_out, int out_size) {
    const float* x      = (const float*)d_in[0];
    const float* keys   = (const float*)d_in[1];
    const float* values = (const float*)d_in[2];
    const float* w1     = (const float*)d_in[3];
    const float* b1     = (const float*)d_in[4];
    const float* w2     = (const float*)d_in[5];
    const float* b2     = (const float*)d_in[6];
    float* out          = (float*)d_out;

    (void)in_sizes; (void)n_in; (void)out_size;

    k_prep_W<<<dim3(8, 8), 256>>>(w1, w2);
    k_prep_aux<<<4, 128>>>(w1, w2, b1, b2);
    k_gemm_q2<<<dim3(4, 64), 256>>>(x);
    k_attention<<<B_ROWS, 256>>>(x, keys, values, out);
}

// round 4
// speedup vs baseline: 1.3567x; 1.3567x over previous
#include <cuda_runtime.h>
#include <cuda_bf16.h>
#include <cstdint>
#include <math.h>

#define B_ROWS 8192
#define KNN    32
#define D      512
#define KP     1536   // 3*D concatenated K for split GEMM

// 1/sqrt(512)
#define SCORE_SCALE 0.044194173824159220f

// -------- device scratch (allocation-free) --------
// B' = [W_hi | W_lo | W_hi] stored [n][k'] (k'-contiguous), n=output col, k=input dim
__device__ __align__(16) __nv_bfloat16 g_Wb[(size_t)D * KP];
// A' = [x_hi | x_hi | x_lo] stored [b][k']
__device__ __align__(16) __nv_bfloat16 g_xa[(size_t)B_ROWS * KP];
__device__ float g_c[D];              // b1 @ w2     [d]
__device__ float g_u[D];              // w1^T @ b2   [d]
__device__ float g_s0;                // b1 . b2
__device__ __align__(16) float g_q2[(size_t)B_ROWS * D];  // x @ W + c

// ---- bf16 mma.sync (sm_80-era; valid on plain sm_103 target) ----
__device__ __forceinline__ void mma_bf16_16816(float* d, const uint32_t* a, const uint32_t* b) {
    asm volatile(
        "mma.sync.aligned.m16n8k16.row.col.f32.bf16.bf16.f32 "
        "{%0,%1,%2,%3}, {%4,%5,%6,%7}, {%8,%9}, {%0,%1,%2,%3};"
        : "+f"(d[0]), "+f"(d[1]), "+f"(d[2]), "+f"(d[3])
        : "r"(a[0]), "r"(a[1]), "r"(a[2]), "r"(a[3]), "r"(b[0]), "r"(b[1]));
}

// ============================================================
// Kernel 1: W[m,n] = sum_e w1[e,m] * w2[e,n]   (512x512x512)
// epilogue: bf16 split -> g_Wb[n][k'] at k'=m (hi), m+512 (lo), m+1024 (hi)
// ============================================================
__global__ __launch_bounds__(256) void k_prep_W(const float* __restrict__ w1,
                                                const float* __restrict__ w2) {
    __shared__ __align__(16) float As[16][64];
    __shared__ __align__(16) float Bs[16][64];
    const int t  = threadIdx.x;
    const int tx = t & 15;
    const int ty = t >> 4;
    const int m0 = blockIdx.y * 64;
    const int n0 = blockIdx.x * 64;

    const int lr = t >> 4;
    const int lc = (t & 15) * 4;

    float acc[4][4];
#pragma unroll
    for (int i = 0; i < 4; i++)
#pragma unroll
        for (int j = 0; j < 4; j++) acc[i][j] = 0.f;

    for (int k0 = 0; k0 < D; k0 += 16) {
        float4 a = *(const float4*)(w1 + (size_t)(k0 + lr) * D + m0 + lc);
        float4 b = *(const float4*)(w2 + (size_t)(k0 + lr) * D + n0 + lc);
        *(float4*)&As[lr][lc] = a;
        *(float4*)&Bs[lr][lc] = b;
        __syncthreads();
#pragma unroll
        for (int k = 0; k < 16; k++) {
            float ar[4], br[4];
#pragma unroll
            for (int i = 0; i < 4; i++) ar[i] = As[k][ty * 4 + i];
#pragma unroll
            for (int j = 0; j < 4; j++) br[j] = Bs[k][tx * 4 + j];
#pragma unroll
            for (int i = 0; i < 4; i++)
#pragma unroll
                for (int j = 0; j < 4; j++) acc[i][j] += ar[i] * br[j];
        }
        __syncthreads();
    }
#pragma unroll
    for (int i = 0; i < 4; i++) {
        const int m = m0 + ty * 4 + i;   // k' index
#pragma unroll
        for (int j = 0; j < 4; j++) {
            const int n = n0 + tx * 4 + j;
            float w = acc[i][j];
            __nv_bfloat16 hi = __float2bfloat16_rn(w);
            __nv_bfloat16 lo = __float2bfloat16_rn(w - __bfloat162float(hi));
            __nv_bfloat16* row = g_Wb + (size_t)n * KP;
            row[m]        = hi;
            row[m + 512]  = lo;
            row[m + 1024] = hi;
        }
    }
}

// ============================================================
// Kernel 2: c[d], u[d], s0
// ============================================================
__global__ void k_prep_aux(const float* __restrict__ w1,
                           const float* __restrict__ w2,
                           const float* __restrict__ b1,
                           const float* __restrict__ b2) {
    const int d = blockIdx.x * blockDim.x + threadIdx.x;
    float cacc = 0.f, uacc = 0.f;
#pragma unroll 8
    for (int e = 0; e < D; e++) {
        cacc += b1[e] * w2[(size_t)e * D + d];
        uacc += b2[e] * w1[(size_t)e * D + d];
    }
    g_c[d] = cacc;
    g_u[d] = uacc;
    if (blockIdx.x == 0 && threadIdx.x < 32) {
        float s = 0.f;
        for (int e = threadIdx.x; e < D; e += 32) s += b1[e] * b2[e];
#pragma unroll
        for (int o = 16; o; o >>= 1) s += __shfl_xor_sync(0xffffffffu, s, o);
        if (threadIdx.x == 0) g_s0 = s;
    }
}

// ============================================================
// Kernel 2b: split x -> g_xa = [x_hi | x_hi | x_lo] per row.
// one block per 4 rows: 256 threads, 8 floats each (=2 rows? no:
// 4 rows * 512 = 2048 floats / 256 threads = 8 floats/thread).
// ============================================================
__global__ __launch_bounds__(256) void k_split_x(const float* __restrict__ x) {
    // each thread: 8 consecutive floats of one row
    const size_t gidx = ((size_t)blockIdx.x * 256 + threadIdx.x) * 8;  // in x
    const size_t row  = gidx >> 9;          // /512
    const size_t col  = gidx & 511;
    float4 v0 = *(const float4*)(x + gidx);
    float4 v1 = *(const float4*)(x + gidx + 4);
    float f[8] = {v0.x, v0.y, v0.z, v0.w, v1.x, v1.y, v1.z, v1.w};
    __nv_bfloat16 hi[8], lo[8];
#pragma unroll
    for (int i = 0; i < 8; i++) {
        hi[i] = __float2bfloat16_rn(f[i]);
        lo[i] = __float2bfloat16_rn(f[i] - __bfloat162float(hi[i]));
    }
    __nv_bfloat16* dst = g_xa + row * KP + col;
    *(uint4*)(dst)        = *(const uint4*)hi;
    *(uint4*)(dst + 512)  = *(const uint4*)hi;
    *(uint4*)(dst + 1024) = *(const uint4*)lo;
}

// ============================================================
// Kernel 3: q2 = A' @ B'^T + c  (8192 x 512 x 1536 bf16 HMMA)
// BM=128 BN=128 BK=32, 256 threads (8 warps, 2m x 4n), warp tile 64x32.
// mma.sync m16n8k16: per warp 4 mtiles x 4 ntiles.
// grid: (4, 64)
// ============================================================
#define BKP 40   // padded smem row stride (bf16) = 80 bytes

__global__ __launch_bounds__(256) void k_gemm_q2_mma() {
    __shared__ __align__(16) __nv_bfloat16 As[128 * BKP];
    __shared__ __align__(16) __nv_bfloat16 Bs[128 * BKP];

    const int t    = threadIdx.x;
    const int lane = t & 31;
    const int wid  = t >> 5;
    const int wm   = wid & 1;        // 0..1
    const int wn   = wid >> 1;       // 0..3
    const int gid  = lane >> 2;      // 0..7
    const int qid  = lane & 3;       // 0..3

    const int n0 = blockIdx.x * 128;
    const int m0 = blockIdx.y * 128;

    // global load indices: 512 uint4 per tile for each of A,B; 2 per thread
    const int jA0 = t * 2;
    // j -> row = j>>2, chunk = j&3 (8 bf16 per chunk)
    const int arow0 = jA0 >> 2, ach0 = (jA0 & 3) * 8;
    const int arow1 = (jA0 + 1) >> 2, ach1 = ((jA0 + 1) & 3) * 8;

    const __nv_bfloat16* Abase = g_xa + (size_t)(m0 + arow0) * KP + ach0;
    const __nv_bfloat16* Abase1 = g_xa + (size_t)(m0 + arow1) * KP + ach1;
    const __nv_bfloat16* Bbase = g_Wb + (size_t)(n0 + arow0) * KP + ach0;
    const __nv_bfloat16* Bbase1 = g_Wb + (size_t)(n0 + arow1) * KP + ach1;

    float acc[4][4][4];
#pragma unroll
    for (int i = 0; i < 4; i++)
#pragma unroll
        for (int j = 0; j < 4; j++)
#pragma unroll
            for (int r = 0; r < 4; r++) acc[i][j][r] = 0.f;

    // prefetch first tile
    uint4 pa0 = *(const uint4*)(Abase);
    uint4 pa1 = *(const uint4*)(Abase1);
    uint4 pb0 = *(const uint4*)(Bbase);
    uint4 pb1 = *(const uint4*)(Bbase1);

    for (int kt = 0; kt < KP; kt += 32) {
        // commit prefetched tile to smem
        *(uint4*)&As[arow0 * BKP + ach0] = pa0;
        *(uint4*)&As[arow1 * BKP + ach1] = pa1;
        *(uint4*)&Bs[arow0 * BKP + ach0] = pb0;
        *(uint4*)&Bs[arow1 * BKP + ach1] = pb1;
        __syncthreads();

        if (kt + 32 < KP) {
            pa0 = *(const uint4*)(Abase + kt + 32);
            pa1 = *(const uint4*)(Abase1 + kt + 32);
            pb0 = *(const uint4*)(Bbase + kt + 32);
            pb1 = *(const uint4*)(Bbase1 + kt + 32);
        }

#pragma unroll
        for (int ks = 0; ks < 2; ks++) {
            const int k0 = ks * 16 + qid * 2;
            uint32_t afrag[4][4];
            uint32_t bfrag[4][2];
#pragma unroll
            for (int mt = 0; mt < 4; mt++) {
                const int mloc = wm * 64 + mt * 16 + gid;
                const __nv_bfloat16* ap = &As[mloc * BKP];
                afrag[mt][0] = *(const uint32_t*)(ap + k0);
                afrag[mt][1] = *(const uint32_t*)(ap + 8 * BKP + k0);
                afrag[mt][2] = *(const uint32_t*)(ap + k0 + 8);
                afrag[mt][3] = *(const uint32_t*)(ap + 8 * BKP + k0 + 8);
            }
#pragma unroll
            for (int nt = 0; nt < 4; nt++) {
                const int nloc = wn * 32 + nt * 8 + gid;
                const __nv_bfloat16* bp = &Bs[nloc * BKP];
                bfrag[nt][0] = *(const uint32_t*)(bp + k0);
                bfrag[nt][1] = *(const uint32_t*)(bp + k0 + 8);
            }
#pragma unroll
            for (int mt = 0; mt < 4; mt++)
#pragma unroll
                for (int nt = 0; nt < 4; nt++)
                    mma_bf16_16816(acc[mt][nt], afrag[mt], bfrag[nt]);
        }
        __syncthreads();
    }

    // epilogue: d0=D[gid][q*2], d1=+1, d2=D[gid+8][q*2], d3=+1
#pragma unroll
    for (int mt = 0; mt < 4; mt++) {
        const int row0 = m0 + wm * 64 + mt * 16 + gid;
#pragma unroll
        for (int nt = 0; nt < 4; nt++) {
            const int col0 = n0 + wn * 32 + nt * 8 + qid * 2;
            const float c0 = g_c[col0], c1 = g_c[col0 + 1];
            float2 v0 = make_float2(acc[mt][nt][0] + c0, acc[mt][nt][1] + c1);
            float2 v1 = make_float2(acc[mt][nt][2] + c0, acc[mt][nt][3] + c1);
            *(float2*)(g_q2 + (size_t)row0 * D + col0)       = v0;
            *(float2*)(g_q2 + (size_t)(row0 + 8) * D + col0) = v1;
        }
    }
}

// ============================================================
// Kernel 4: per-row attention + blend (unchanged; DRAM-bound @86%)
// ============================================================
__global__ __launch_bounds__(256) void k_attention(const float* __restrict__ x,
                                                   const float* __restrict__ keys,
                                                   const float* __restrict__ values,
                                                   float* __restrict__ out) {
    __shared__ __align__(16) float xs[D];
    __shared__ __align__(16) float q2s[D];
    __shared__ float att_s[KNN];
    __shared__ float warp_red[8];
    __shared__ float qb2_sh;

    const int b    = blockIdx.x;
    const int t    = threadIdx.x;
    const int lane = t & 31;
    const int w    = t >> 5;

    if (t < 128) {
        ((float4*)xs)[t] = ((const float4*)(x + (size_t)b * D))[t];
    } else {
        ((float4*)q2s)[t - 128] = ((const float4*)(g_q2 + (size_t)b * D))[t - 128];
    }
    __syncthreads();

    {
        float p = xs[t] * g_u[t] + xs[t + 256] * g_u[t + 256];
#pragma unroll
        for (int o = 16; o; o >>= 1) p += __shfl_xor_sync(0xffffffffu, p, o);
        if (lane == 0) warp_red[w] = p;
        __syncthreads();
        if (t == 0) {
            float s = 0.f;
#pragma unroll
            for (int i = 0; i < 8; i++) s += warp_red[i];
            qb2_sh = s + g_s0;
        }
        __syncthreads();
    }

    const float4* q2s4 = (const float4*)q2s;
    const float* kbase = keys + (size_t)b * KNN * D;
#pragma unroll
    for (int kk = 0; kk < 4; kk++) {
        const int k = w * 4 + kk;
        const float4* kr = (const float4*)(kbase + (size_t)k * D);
        float p = 0.f;
#pragma unroll
        for (int i = 0; i < 4; i++) {
            float4 kv = kr[lane + 32 * i];
            float4 qv = q2s4[lane + 32 * i];
            p += kv.x * qv.x + kv.y * qv.y + kv.z * qv.z + kv.w * qv.w;
        }
#pragma unroll
        for (int o = 16; o; o >>= 1) p += __shfl_xor_sync(0xffffffffu, p, o);
        if (lane == 0) att_s[k] = (p + qb2_sh) * SCORE_SCALE;
    }
    __syncthreads();

    if (t < 32) {
        float s = att_s[t];
        float m = s;
#pragma unroll
        for (int o = 16; o; o >>= 1) m = fmaxf(m, __shfl_xor_sync(0xffffffffu, m, o));
        float e = expf(s - m);
        float sum = e;
#pragma unroll
        for (int o = 16; o; o >>= 1) sum += __shfl_xor_sync(0xffffffffu, sum, o);
        att_s[t] = e / sum;
    }
    __syncthreads();

    const float* vbase = values + (size_t)b * KNN * D;
    float ax = 0.f, ay = 0.f;
#pragma unroll 4
    for (int k = 0; k < KNN; k++) {
        float a = att_s[k];
        float2 v = *(const float2*)(vbase + (size_t)k * D + 2 * t);
        ax += a * v.x;
        ay += a * v.y;
    }
    float2 xv = *(const float2*)&xs[2 * t];
    float2 o;
    o.x = 0.5f * xv.x + 0.5f * ax;
    o.y = 0.5f * xv.y + 0.5f * ay;
    *(float2*)(out + (size_t)b * D + 2 * t) = o;
}

// ============================================================
extern "C" void kernel_launch(void* const* d_in, const int* in_sizes, int n_in,
                              void* d_out, int out_size) {
    const float* x      = (const float*)d_in[0];
    const float* keys   = (const float*)d_in[1];
    const float* values = (const float*)d_in[2];
    const float* w1     = (const float*)d_in[3];
    const float* b1     = (const float*)d_in[4];
    const float* w2     = (const float*)d_in[5];
    const float* b2     = (const float*)d_in[6];
    float* out          = (float*)d_out;

    (void)in_sizes; (void)n_in; (void)out_size;

    k_prep_W<<<dim3(8, 8), 256>>>(w1, w2);
    k_prep_aux<<<4, 128>>>(w1, w2, b1, b2);
    k_split_x<<<(B_ROWS * D) / (256 * 8), 256>>>(x);
    k_gemm_q2_mma<<<dim3(4, 64), 256>>>();
    k_attention<<<B_ROWS, 256>>>(x, keys, values, out);
}

// round 5
// speedup vs baseline: 1.7013x; 1.2540x over previous
#include <cuda_runtime.h>
#include <cuda_bf16.h>
#include <cstdint>
#include <math.h>

#define B_ROWS 8192
#define KNN    32
#define D      512
#define KP     1536   // 3*D concatenated K for split GEMM

// 1/sqrt(512)
#define SCORE_SCALE 0.044194173824159220f

// -------- device scratch (allocation-free) --------
__device__ __align__(16) __nv_bfloat16 g_Wb[(size_t)D * KP];     // [n][k']  = [W_hi|W_lo|W_hi]
__device__ __align__(16) __nv_bfloat16 g_xa[(size_t)B_ROWS * KP]; // [b][k'] = [x_hi|x_hi|x_lo]
__device__ float g_c[D];
__device__ float g_u[D];
__device__ float g_s0;
__device__ __align__(16) float g_q2[(size_t)B_ROWS * D];

// ---- PTX helpers ----
__device__ __forceinline__ uint32_t smem_to_u32(const void* p) {
    uint32_t a;
    asm("{ .reg .u64 tmp; cvta.to.shared.u64 tmp, %1; cvt.u32.u64 %0, tmp; }"
        : "=r"(a) : "l"(p));
    return a;
}
__device__ __forceinline__ void mma_bf16_16816(float* d, const uint32_t* a, const uint32_t* b) {
    asm volatile(
        "mma.sync.aligned.m16n8k16.row.col.f32.bf16.bf16.f32 "
        "{%0,%1,%2,%3}, {%4,%5,%6,%7}, {%8,%9}, {%0,%1,%2,%3};"
        : "+f"(d[0]), "+f"(d[1]), "+f"(d[2]), "+f"(d[3])
        : "r"(a[0]), "r"(a[1]), "r"(a[2]), "r"(a[3]), "r"(b[0]), "r"(b[1]));
}
__device__ __forceinline__ void ldsm_x4(uint32_t& r0, uint32_t& r1, uint32_t& r2, uint32_t& r3,
                                        uint32_t addr) {
    asm volatile("ldmatrix.sync.aligned.m8n8.x4.shared.b16 {%0,%1,%2,%3}, [%4];"
                 : "=r"(r0), "=r"(r1), "=r"(r2), "=r"(r3) : "r"(addr));
}
#define CP_ASYNC_16(dst, src) \
    asm volatile("cp.async.cg.shared.global [%0], [%1], 16;" :: "r"(dst), "l"(src))
#define CP_COMMIT() asm volatile("cp.async.commit_group;" ::: "memory")
#define CP_WAIT1()  asm volatile("cp.async.wait_group 1;" ::: "memory")

// ============================================================
// Kernel 1: W[m,n] = sum_e w1[e,m]*w2[e,n]; epilogue bf16 split,
// packed 8-byte stores into g_Wb[n][k'].
// ============================================================
__global__ __launch_bounds__(256) void k_prep_W(const float* __restrict__ w1,
                                                const float* __restrict__ w2) {
    __shared__ __align__(16) float As[16][64];
    __shared__ __align__(16) float Bs[16][64];
    const int t  = threadIdx.x;
    const int tx = t & 15;
    const int ty = t >> 4;
    const int m0 = blockIdx.y * 64;
    const int n0 = blockIdx.x * 64;

    const int lr = t >> 4;
    const int lc = (t & 15) * 4;

    float acc[4][4];
#pragma unroll
    for (int i = 0; i < 4; i++)
#pragma unroll
        for (int j = 0; j < 4; j++) acc[i][j] = 0.f;

    for (int k0 = 0; k0 < D; k0 += 16) {
        float4 a = *(const float4*)(w1 + (size_t)(k0 + lr) * D + m0 + lc);
        float4 b = *(const float4*)(w2 + (size_t)(k0 + lr) * D + n0 + lc);
        *(float4*)&As[lr][lc] = a;
        *(float4*)&Bs[lr][lc] = b;
        __syncthreads();
#pragma unroll
        for (int k = 0; k < 16; k++) {
            float ar[4], br[4];
#pragma unroll
            for (int i = 0; i < 4; i++) ar[i] = As[k][ty * 4 + i];
#pragma unroll
            for (int j = 0; j < 4; j++) br[j] = Bs[k][tx * 4 + j];
#pragma unroll
            for (int i = 0; i < 4; i++)
#pragma unroll
                for (int j = 0; j < 4; j++) acc[i][j] += ar[i] * br[j];
        }
        __syncthreads();
    }
    // packed split store: 4 consecutive m (k') per 8B store
    const int mbase = m0 + ty * 4;
#pragma unroll
    for (int j = 0; j < 4; j++) {
        const int n = n0 + tx * 4 + j;
        __nv_bfloat16 h4[4], l4[4];
#pragma unroll
        for (int i = 0; i < 4; i++) {
            float w = acc[i][j];
            h4[i] = __float2bfloat16_rn(w);
            l4[i] = __float2bfloat16_rn(w - __bfloat162float(h4[i]));
        }
        __nv_bfloat16* row = g_Wb + (size_t)n * KP;
        *(uint2*)(row + mbase)        = *(const uint2*)h4;
        *(uint2*)(row + mbase + 512)  = *(const uint2*)l4;
        *(uint2*)(row + mbase + 1024) = *(const uint2*)h4;
    }
}

// ============================================================
// Kernel 2: c[d], u[d], s0 — 32 blocks, 16 threads per d.
// ============================================================
__global__ __launch_bounds__(256) void k_prep_aux(const float* __restrict__ w1,
                                                  const float* __restrict__ w2,
                                                  const float* __restrict__ b1,
                                                  const float* __restrict__ b2) {
    const int tid = threadIdx.x;
    const int dl = tid >> 4;     // 0..15
    const int el = tid & 15;     // 0..15
    const int d = blockIdx.x * 16 + dl;
    float cacc = 0.f, uacc = 0.f;
#pragma unroll 4
    for (int e = el; e < D; e += 16) {
        cacc += b1[e] * w2[(size_t)e * D + d];
        uacc += b2[e] * w1[(size_t)e * D + d];
    }
#pragma unroll
    for (int o = 8; o; o >>= 1) {
        cacc += __shfl_down_sync(0xffffffffu, cacc, o, 16);
        uacc += __shfl_down_sync(0xffffffffu, uacc, o, 16);
    }
    if (el == 0) { g_c[d] = cacc; g_u[d] = uacc; }
    if (blockIdx.x == 0 && tid < 32) {
        float s = 0.f;
        for (int e = tid; e < D; e += 32) s += b1[e] * b2[e];
#pragma unroll
        for (int o = 16; o; o >>= 1) s += __shfl_xor_sync(0xffffffffu, s, o);
        if (tid == 0) g_s0 = s;
    }
}

// ============================================================
// Kernel 2b: split x -> g_xa = [x_hi | x_hi | x_lo] per row.
// ============================================================
__global__ __launch_bounds__(256) void k_split_x(const float* __restrict__ x) {
    const size_t gidx = ((size_t)blockIdx.x * 256 + threadIdx.x) * 8;
    const size_t row  = gidx >> 9;
    const size_t col  = gidx & 511;
    float4 v0 = *(const float4*)(x + gidx);
    float4 v1 = *(const float4*)(x + gidx + 4);
    float f[8] = {v0.x, v0.y, v0.z, v0.w, v1.x, v1.y, v1.z, v1.w};
    __nv_bfloat16 hi[8], lo[8];
#pragma unroll
    for (int i = 0; i < 8; i++) {
        hi[i] = __float2bfloat16_rn(f[i]);
        lo[i] = __float2bfloat16_rn(f[i] - __bfloat162float(hi[i]));
    }
    __nv_bfloat16* dst = g_xa + row * KP + col;
    *(uint4*)(dst)        = *(const uint4*)hi;
    *(uint4*)(dst + 512)  = *(const uint4*)hi;
    *(uint4*)(dst + 1024) = *(const uint4*)lo;
}

// ============================================================
// Kernel 3: q2 = A' @ B'^T + c  (8192 x 512 x 1536 bf16 HMMA)
// BM=256 BN=128 BK=64, 512 threads (4m x 4n warps, warp tile 64x32),
// ldmatrix.x4 frags, SW128-swizzled smem, cp.async 2-stage pipeline.
// grid (4, 32) = 128 CTAs = one wave.
// ============================================================
#define BM 256
#define BN 128
#define BK 64
#define STAGE_A (BM * 128)            // 32768 B
#define STAGE_B (BN * 128)            // 16384 B
#define STAGE   (STAGE_A + STAGE_B)   // 49152 B
#define GEMM_SMEM (2 * STAGE)         // 98304 B
#define NKT (KP / BK)                 // 24

__global__ __launch_bounds__(512, 1) void k_gemm_q2_mma() {
    extern __shared__ char smem[];
    const uint32_t sbase = smem_to_u32(smem);

    const int t    = threadIdx.x;
    const int lane = t & 31;
    const int wid  = t >> 5;       // 0..15
    const int wm   = wid & 3;      // m warp (64 rows each)
    const int wn   = wid >> 2;     // n warp (32 cols each)
    const int gid  = lane >> 2;
    const int qid  = lane & 3;

    const int n0 = blockIdx.x * BN;
    const int m0 = blockIdx.y * BM;

    // cp.async assignments
    const int arow = t >> 1;           // 0..255
    const int au0  = (t & 1) * 4;      // 16B-unit start (0 or 4)
    const int brow = t >> 2;           // 0..127
    const int bu0  = (t & 3) * 2;      // 16B-unit start

    const __nv_bfloat16* Ag = g_xa + (size_t)(m0 + arow) * KP + au0 * 8;
    const __nv_bfloat16* Bg = g_Wb + (size_t)(n0 + brow) * KP + bu0 * 8;

    uint32_t adst[4], bdst[2];
#pragma unroll
    for (int i = 0; i < 4; i++) {
        const int u = au0 + i;
        adst[i] = sbase + arow * 128 + (((uint32_t)(u ^ (arow & 7))) << 4);
    }
#pragma unroll
    for (int i = 0; i < 2; i++) {
        const int u = bu0 + i;
        bdst[i] = sbase + STAGE_A + brow * 128 + (((uint32_t)(u ^ (brow & 7))) << 4);
    }

    // ldmatrix lane-dependent address components
    const int lr   = lane & 7;
    const int half = (lane >> 3) & 1;
    const int kh   = (lane >> 4) & 1;
    // A: row within tile for each mtile
    int arow_f[4];
#pragma unroll
    for (int mt = 0; mt < 4; mt++) arow_f[mt] = wm * 64 + mt * 16 + half * 8 + lr;
    // B: matrix idx = lane>>3: ntl offset (bit1), khalf (bit0)
    const int bmtx   = lane >> 3;          // 0..3
    const int bntoff = bmtx >> 1;          // 0 or 1
    const int bkh    = bmtx & 1;
    int brow_f[2];
#pragma unroll
    for (int p = 0; p < 2; p++) brow_f[p] = wn * 32 + (p * 2 + bntoff) * 8 + lr;

    float acc[4][4][4];
#pragma unroll
    for (int i = 0; i < 4; i++)
#pragma unroll
        for (int j = 0; j < 4; j++)
#pragma unroll
            for (int r = 0; r < 4; r++) acc[i][j][r] = 0.f;

    // ---- pipeline ----
    // load stage 0
    {
#pragma unroll
        for (int i = 0; i < 4; i++) CP_ASYNC_16(adst[i], Ag + i * 8);
#pragma unroll
        for (int i = 0; i < 2; i++) CP_ASYNC_16(bdst[i], Bg + i * 8);
        CP_COMMIT();
    }

    for (int kt = 0; kt < NKT; kt++) {
        const int s = kt & 1;
        if (kt + 1 < NKT) {
            const uint32_t soff = (uint32_t)((s ^ 1) * STAGE);
            const int ko = (kt + 1) * BK;
#pragma unroll
            for (int i = 0; i < 4; i++) CP_ASYNC_16(adst[i] + soff, Ag + ko + i * 8);
#pragma unroll
            for (int i = 0; i < 2; i++) CP_ASYNC_16(bdst[i] + soff, Bg + ko + i * 8);
        }
        CP_COMMIT();
        CP_WAIT1();
        __syncthreads();

        const uint32_t Asm = sbase + (uint32_t)(s * STAGE);
        const uint32_t Bsm = Asm + STAGE_A;
#pragma unroll
        for (int ks = 0; ks < 4; ks++) {
            uint32_t af[4][4];
#pragma unroll
            for (int mt = 0; mt < 4; mt++) {
                const int row = arow_f[mt];
                const int u = ks * 2 + kh;
                ldsm_x4(af[mt][0], af[mt][1], af[mt][2], af[mt][3],
                        Asm + row * 128 + (((uint32_t)(u ^ (row & 7))) << 4));
            }
            uint32_t bf[4][2];
#pragma unroll
            for (int p = 0; p < 2; p++) {
                const int row = brow_f[p];
                const int u = ks * 2 + bkh;
                ldsm_x4(bf[p * 2][0], bf[p * 2][1], bf[p * 2 + 1][0], bf[p * 2 + 1][1],
                        Bsm + row * 128 + (((uint32_t)(u ^ (row & 7))) << 4));
            }
#pragma unroll
            for (int mt = 0; mt < 4; mt++)
#pragma unroll
                for (int nt = 0; nt < 4; nt++)
                    mma_bf16_16816(acc[mt][nt], af[mt], bf[nt]);
        }
        __syncthreads();
    }

    // epilogue
#pragma unroll
    for (int mt = 0; mt < 4; mt++) {
        const int row0 = m0 + wm * 64 + mt * 16 + gid;
#pragma unroll
        for (int nt = 0; nt < 4; nt++) {
            const int col0 = n0 + wn * 32 + nt * 8 + qid * 2;
            const float c0 = g_c[col0], c1 = g_c[col0 + 1];
            float2 v0 = make_float2(acc[mt][nt][0] + c0, acc[mt][nt][1] + c1);
            float2 v1 = make_float2(acc[mt][nt][2] + c0, acc[mt][nt][3] + c1);
            *(float2*)(g_q2 + (size_t)row0 * D + col0)       = v0;
            *(float2*)(g_q2 + (size_t)(row0 + 8) * D + col0) = v1;
        }
    }
}

// ============================================================
// Kernel 4: per-row attention + blend (DRAM-bound @86%, unchanged)
// ============================================================
__global__ __launch_bounds__(256) void k_attention(const float* __restrict__ x,
                                                   const float* __restrict__ keys,
                                                   const float* __restrict__ values,
                                                   float* __restrict__ out) {
    __shared__ __align__(16) float xs[D];
    __shared__ __align__(16) float q2s[D];
    __shared__ float att_s[KNN];
    __shared__ float warp_red[8];
    __shared__ float qb2_sh;

    const int b    = blockIdx.x;
    const int t    = threadIdx.x;
    const int lane = t & 31;
    const int w    = t >> 5;

    if (t < 128) {
        ((float4*)xs)[t] = ((const float4*)(x + (size_t)b * D))[t];
    } else {
        ((float4*)q2s)[t - 128] = ((const float4*)(g_q2 + (size_t)b * D))[t - 128];
    }
    __syncthreads();

    {
        float p = xs[t] * g_u[t] + xs[t + 256] * g_u[t + 256];
#pragma unroll
        for (int o = 16; o; o >>= 1) p += __shfl_xor_sync(0xffffffffu, p, o);
        if (lane == 0) warp_red[w] = p;
        __syncthreads();
        if (t == 0) {
            float s = 0.f;
#pragma unroll
            for (int i = 0; i < 8; i++) s += warp_red[i];
            qb2_sh = s + g_s0;
        }
        __syncthreads();
    }

    const float4* q2s4 = (const float4*)q2s;
    const float* kbase = keys + (size_t)b * KNN * D;
#pragma unroll
    for (int kk = 0; kk < 4; kk++) {
        const int k = w * 4 + kk;
        const float4* kr = (const float4*)(kbase + (size_t)k * D);
        float p = 0.f;
#pragma unroll
        for (int i = 0; i < 4; i++) {
            float4 kv = kr[lane + 32 * i];
            float4 qv = q2s4[lane + 32 * i];
            p += kv.x * qv.x + kv.y * qv.y + kv.z * qv.z + kv.w * qv.w;
        }
#pragma unroll
        for (int o = 16; o; o >>= 1) p += __shfl_xor_sync(0xffffffffu, p, o);
        if (lane == 0) att_s[k] = (p + qb2_sh) * SCORE_SCALE;
    }
    __syncthreads();

    if (t < 32) {
        float s = att_s[t];
        float m = s;
#pragma unroll
        for (int o = 16; o; o >>= 1) m = fmaxf(m, __shfl_xor_sync(0xffffffffu, m, o));
        float e = expf(s - m);
        float sum = e;
#pragma unroll
        for (int o = 16; o; o >>= 1) sum += __shfl_xor_sync(0xffffffffu, sum, o);
        att_s[t] = e / sum;
    }
    __syncthreads();

    const float* vbase = values + (size_t)b * KNN * D;
    float ax = 0.f, ay = 0.f;
#pragma unroll 4
    for (int k = 0; k < KNN; k++) {
        float a = att_s[k];
        float2 v = *(const float2*)(vbase + (size_t)k * D + 2 * t);
        ax += a * v.x;
        ay += a * v.y;
    }
    float2 xv = *(const float2*)&xs[2 * t];
    float2 o;
    o.x = 0.5f * xv.x + 0.5f * ax;
    o.y = 0.5f * xv.y + 0.5f * ay;
    *(float2*)(out + (size_t)b * D + 2 * t) = o;
}

// ============================================================
extern "C" void kernel_launch(void* const* d_in, const int* in_sizes, int n_in,
                              void* d_out, int out_size) {
    const float* x      = (const float*)d_in[0];
    const float* keys   = (const float*)d_in[1];
    const float* values = (const float*)d_in[2];
    const float* w1     = (const float*)d_in[3];
    const float* b1     = (const float*)d_in[4];
    const float* w2     = (const float*)d_in[5];
    const float* b2     = (const float*)d_in[6];
    float* out          = (float*)d_out;

    (void)in_sizes; (void)n_in; (void)out_size;

    cudaFuncSetAttribute(k_gemm_q2_mma, cudaFuncAttributeMaxDynamicSharedMemorySize,
                         GEMM_SMEM);

    k_prep_W<<<dim3(8, 8), 256>>>(w1, w2);
    k_prep_aux<<<32, 256>>>(w1, w2, b1, b2);
    k_split_x<<<(B_ROWS * D) / (256 * 8), 256>>>(x);
    k_gemm_q2_mma<<<dim3(4, 32), 512, GEMM_SMEM>>>();
    k_attention<<<B_ROWS, 256>>>(x, keys, values, out);
}

// round 6
// speedup vs baseline: 1.8056x; 1.0613x over previous
#include <cuda_runtime.h>
#include <cuda_bf16.h>
#include <cstdint>
#include <math.h>

#define B_ROWS 8192
#define KNN    32
#define D      512
#define KP     1536   // 3*D concatenated K for split GEMM

// 1/sqrt(512)
#define SCORE_SCALE 0.044194173824159220f

// -------- device scratch (allocation-free) --------
__device__ __align__(16) __nv_bfloat16 g_Wb[(size_t)D * KP];      // [n][k'] = [W_hi|W_lo|W_hi]
__device__ __align__(16) __nv_bfloat16 g_xa[(size_t)B_ROWS * KP]; // [b][k'] = [x_hi|x_hi|x_lo]
__device__ float g_c[D];
__device__ float g_u[D];
__device__ float g_s0;
__device__ __align__(16) float g_q2[(size_t)B_ROWS * D];

// ---- PTX helpers ----
__device__ __forceinline__ uint32_t smem_to_u32(const void* p) {
    uint32_t a;
    asm("{ .reg .u64 tmp; cvta.to.shared.u64 tmp, %1; cvt.u32.u64 %0, tmp; }"
        : "=r"(a) : "l"(p));
    return a;
}
__device__ __forceinline__ void mma_bf16_16816(float* d, const uint32_t* a, const uint32_t* b) {
    asm volatile(
        "mma.sync.aligned.m16n8k16.row.col.f32.bf16.bf16.f32 "
        "{%0,%1,%2,%3}, {%4,%5,%6,%7}, {%8,%9}, {%0,%1,%2,%3};"
        : "+f"(d[0]), "+f"(d[1]), "+f"(d[2]), "+f"(d[3])
        : "r"(a[0]), "r"(a[1]), "r"(a[2]), "r"(a[3]), "r"(b[0]), "r"(b[1]));
}
__device__ __forceinline__ void ldsm_x4(uint32_t& r0, uint32_t& r1, uint32_t& r2, uint32_t& r3,
                                        uint32_t addr) {
    asm volatile("ldmatrix.sync.aligned.m8n8.x4.shared.b16 {%0,%1,%2,%3}, [%4];"
                 : "=r"(r0), "=r"(r1), "=r"(r2), "=r"(r3) : "r"(addr));
}
#define CP_ASYNC_16(dst, src) \
    asm volatile("cp.async.cg.shared.global [%0], [%1], 16;" :: "r"(dst), "l"(src))
#define CP_COMMIT() asm volatile("cp.async.commit_group;" ::: "memory")
#define CP_WAIT1()  asm volatile("cp.async.wait_group 1;" ::: "memory")

// ============================================================
// Kernel 1: W[m,n] = sum_e w1[e,m]*w2[e,n]  — 32x32 tiles,
// grid 16x16 = 256 blocks, 256 threads, 4 acc/thread.
// Epilogue: bf16 split, packed 8B stores into g_Wb[n][k'].
// ============================================================
__global__ __launch_bounds__(256) void k_prep_W(const float* __restrict__ w1,
                                                const float* __restrict__ w2) {
    __shared__ __align__(16) float As[32][36];  // [k][m], stride 36 keeps float4 alignment
    __shared__ __align__(16) float Bs[32][36];  // [k][n]
    const int t  = threadIdx.x;
    const int tx = t & 31;       // n within tile
    const int ty = t >> 5;       // m group (4 rows each)
    const int m0 = blockIdx.y * 32;
    const int n0 = blockIdx.x * 32;

    const int lrow = t >> 3;         // 0..31 (k row)
    const int lcol = (t & 7) * 4;    // 0..28

    float acc[4] = {0.f, 0.f, 0.f, 0.f};

    for (int k0 = 0; k0 < D; k0 += 32) {
        float4 a = *(const float4*)(w1 + (size_t)(k0 + lrow) * D + m0 + lcol);
        float4 b = *(const float4*)(w2 + (size_t)(k0 + lrow) * D + n0 + lcol);
        *(float4*)&As[lrow][lcol] = a;
        *(float4*)&Bs[lrow][lcol] = b;
        __syncthreads();
#pragma unroll
        for (int k = 0; k < 32; k++) {
            const float bv = Bs[k][tx];
#pragma unroll
            for (int i = 0; i < 4; i++) acc[i] += As[k][ty * 4 + i] * bv;
        }
        __syncthreads();
    }

    // packed split store: 4 consecutive k'(=m) per 8B store
    const int mbase = m0 + ty * 4;
    const int n = n0 + tx;
    __nv_bfloat16 h4[4], l4[4];
#pragma unroll
    for (int i = 0; i < 4; i++) {
        h4[i] = __float2bfloat16_rn(acc[i]);
        l4[i] = __float2bfloat16_rn(acc[i] - __bfloat162float(h4[i]));
    }
    __nv_bfloat16* row = g_Wb + (size_t)n * KP;
    *(uint2*)(row + mbase)        = *(const uint2*)h4;
    *(uint2*)(row + mbase + 512)  = *(const uint2*)l4;
    *(uint2*)(row + mbase + 1024) = *(const uint2*)h4;
}

// ============================================================
// Kernel 2: c[d], u[d], s0 — 32 blocks, 16 threads per d.
// ============================================================
__global__ __launch_bounds__(256) void k_prep_aux(const float* __restrict__ w1,
                                                  const float* __restrict__ w2,
                                                  const float* __restrict__ b1,
                                                  const float* __restrict__ b2) {
    const int tid = threadIdx.x;
    const int dl = tid >> 4;
    const int el = tid & 15;
    const int d = blockIdx.x * 16 + dl;
    float cacc = 0.f, uacc = 0.f;
#pragma unroll 4
    for (int e = el; e < D; e += 16) {
        cacc += b1[e] * w2[(size_t)e * D + d];
        uacc += b2[e] * w1[(size_t)e * D + d];
    }
#pragma unroll
    for (int o = 8; o; o >>= 1) {
        cacc += __shfl_down_sync(0xffffffffu, cacc, o, 16);
        uacc += __shfl_down_sync(0xffffffffu, uacc, o, 16);
    }
    if (el == 0) { g_c[d] = cacc; g_u[d] = uacc; }
    if (blockIdx.x == 0 && tid < 32) {
        float s = 0.f;
        for (int e = tid; e < D; e += 32) s += b1[e] * b2[e];
#pragma unroll
        for (int o = 16; o; o >>= 1) s += __shfl_xor_sync(0xffffffffu, s, o);
        if (tid == 0) g_s0 = s;
    }
}

// ============================================================
// Kernel 2b: split x -> g_xa = [x_hi | x_hi | x_lo] per row.
// ============================================================
__global__ __launch_bounds__(256) void k_split_x(const float* __restrict__ x) {
    const size_t gidx = ((size_t)blockIdx.x * 256 + threadIdx.x) * 8;
    const size_t row  = gidx >> 9;
    const size_t col  = gidx & 511;
    float4 v0 = *(const float4*)(x + gidx);
    float4 v1 = *(const float4*)(x + gidx + 4);
    float f[8] = {v0.x, v0.y, v0.z, v0.w, v1.x, v1.y, v1.z, v1.w};
    __nv_bfloat16 hi[8], lo[8];
#pragma unroll
    for (int i = 0; i < 8; i++) {
        hi[i] = __float2bfloat16_rn(f[i]);
        lo[i] = __float2bfloat16_rn(f[i] - __bfloat162float(hi[i]));
    }
    __nv_bfloat16* dst = g_xa + row * KP + col;
    *(uint4*)(dst)        = *(const uint4*)hi;
    *(uint4*)(dst + 512)  = *(const uint4*)hi;
    *(uint4*)(dst + 1024) = *(const uint4*)lo;
}

// ============================================================
// Kernel 3: q2 = A' @ B'^T + c  (8192 x 512 x 1536 bf16 HMMA)
// BM=128 BN=128 BK=64, 256 threads (2m x 4n warps, warp tile 64x32),
// ldmatrix.x4 frags, SW128 swizzle, 3-stage cp.async pipeline.
// grid (4, 64) = 256 CTAs -> 2 CTAs/SM.
// ============================================================
#define BM 128
#define BN 128
#define BK 64
#define STAGE_A (BM * 128)            // 16384 B
#define STAGE_B (BN * 128)            // 16384 B
#define STAGE   (STAGE_A + STAGE_B)   // 32768 B
#define NSTAGE  3
#define GEMM_SMEM (NSTAGE * STAGE)    // 98304 B
#define NKT (KP / BK)                 // 24

__global__ __launch_bounds__(256, 2) void k_gemm_q2_mma() {
    extern __shared__ char smem[];
    const uint32_t sbase = smem_to_u32(smem);

    const int t    = threadIdx.x;
    const int lane = t & 31;
    const int wid  = t >> 5;       // 0..7
    const int wm   = wid & 1;      // m warp (64 rows each)
    const int wn   = wid >> 1;     // n warp (32 cols each)
    const int gid  = lane >> 2;
    const int qid  = lane & 3;

    const int n0 = blockIdx.x * BN;
    const int m0 = blockIdx.y * BM;

    // cp.async assignments: A,B each 16KB/stage = 1024 x 16B; 4 per thread each
    const int row_ld = t >> 1;         // 0..127
    const int u0     = (t & 1) * 4;    // 16B-unit start (0 or 4)

    const __nv_bfloat16* Ag = g_xa + (size_t)(m0 + row_ld) * KP + u0 * 8;
    const __nv_bfloat16* Bg = g_Wb + (size_t)(n0 + row_ld) * KP + u0 * 8;

    uint32_t adst[4], bdst[4];
#pragma unroll
    for (int i = 0; i < 4; i++) {
        const int u = u0 + i;
        const uint32_t sw = ((uint32_t)(u ^ (row_ld & 7))) << 4;
        adst[i] = sbase + row_ld * 128 + sw;
        bdst[i] = sbase + STAGE_A + row_ld * 128 + sw;
    }

    // ldmatrix lane-dependent addresses
    const int lr   = lane & 7;
    const int half = (lane >> 3) & 1;
    const int kh   = (lane >> 4) & 1;
    int arow_f[4];
#pragma unroll
    for (int mt = 0; mt < 4; mt++) arow_f[mt] = wm * 64 + mt * 16 + half * 8 + lr;
    const int bmtx   = lane >> 3;
    const int bntoff = bmtx >> 1;
    const int bkh    = bmtx & 1;
    int brow_f[2];
#pragma unroll
    for (int p = 0; p < 2; p++) brow_f[p] = wn * 32 + (p * 2 + bntoff) * 8 + lr;

    float acc[4][4][4];
#pragma unroll
    for (int i = 0; i < 4; i++)
#pragma unroll
        for (int j = 0; j < 4; j++)
#pragma unroll
            for (int r = 0; r < 4; r++) acc[i][j][r] = 0.f;

    // ---- prologue: load stages 0 and 1 ----
#pragma unroll
    for (int s = 0; s < 2; s++) {
        const uint32_t soff = (uint32_t)(s * STAGE);
        const int ko = s * BK;
#pragma unroll
        for (int i = 0; i < 4; i++) CP_ASYNC_16(adst[i] + soff, Ag + ko + i * 8);
#pragma unroll
        for (int i = 0; i < 4; i++) CP_ASYNC_16(bdst[i] + soff, Bg + ko + i * 8);
        CP_COMMIT();
    }

    for (int kt = 0; kt < NKT; kt++) {
        CP_WAIT1();
        __syncthreads();

        const int s = kt % NSTAGE;
        const uint32_t Asm = sbase + (uint32_t)(s * STAGE);
        const uint32_t Bsm = Asm + STAGE_A;
#pragma unroll
        for (int ks = 0; ks < 4; ks++) {
            uint32_t af[4][4];
#pragma unroll
            for (int mt = 0; mt < 4; mt++) {
                const int row = arow_f[mt];
                const int u = ks * 2 + kh;
                ldsm_x4(af[mt][0], af[mt][1], af[mt][2], af[mt][3],
                        Asm + row * 128 + (((uint32_t)(u ^ (row & 7))) << 4));
            }
            uint32_t bf[4][2];
#pragma unroll
            for (int p = 0; p < 2; p++) {
                const int row = brow_f[p];
                const int u = ks * 2 + bkh;
                ldsm_x4(bf[p * 2][0], bf[p * 2][1], bf[p * 2 + 1][0], bf[p * 2 + 1][1],
                        Bsm + row * 128 + (((uint32_t)(u ^ (row & 7))) << 4));
            }
#pragma unroll
            for (int mt = 0; mt < 4; mt++)
#pragma unroll
                for (int nt = 0; nt < 4; nt++)
                    mma_bf16_16816(acc[mt][nt], af[mt], bf[nt]);
        }

        // issue load for stage kt+2
        if (kt + 2 < NKT) {
            const uint32_t soff = (uint32_t)(((kt + 2) % NSTAGE) * STAGE);
            const int ko = (kt + 2) * BK;
#pragma unroll
            for (int i = 0; i < 4; i++) CP_ASYNC_16(adst[i] + soff, Ag + ko + i * 8);
#pragma unroll
            for (int i = 0; i < 4; i++) CP_ASYNC_16(bdst[i] + soff, Bg + ko + i * 8);
        }
        CP_COMMIT();
    }

    // epilogue
#pragma unroll
    for (int mt = 0; mt < 4; mt++) {
        const int row0 = m0 + wm * 64 + mt * 16 + gid;
#pragma unroll
        for (int nt = 0; nt < 4; nt++) {
            const int col0 = n0 + wn * 32 + nt * 8 + qid * 2;
            const float c0 = g_c[col0], c1 = g_c[col0 + 1];
            float2 v0 = make_float2(acc[mt][nt][0] + c0, acc[mt][nt][1] + c1);
            float2 v1 = make_float2(acc[mt][nt][2] + c0, acc[mt][nt][3] + c1);
            *(float2*)(g_q2 + (size_t)row0 * D + col0)       = v0;
            *(float2*)(g_q2 + (size_t)(row0 + 8) * D + col0) = v1;
        }
    }
}

// ============================================================
// Kernel 4: per-row attention + blend (DRAM-bound @86%, unchanged)
// ============================================================
__global__ __launch_bounds__(256) void k_attention(const float* __restrict__ x,
                                                   const float* __restrict__ keys,
                                                   const float* __restrict__ values,
                                                   float* __restrict__ out) {
    __shared__ __align__(16) float xs[D];
    __shared__ __align__(16) float q2s[D];
    __shared__ float att_s[KNN];
    __shared__ float warp_red[8];
    __shared__ float qb2_sh;

    const int b    = blockIdx.x;
    const int t    = threadIdx.x;
    const int lane = t & 31;
    const int w    = t >> 5;

    if (t < 128) {
        ((float4*)xs)[t] = ((const float4*)(x + (size_t)b * D))[t];
    } else {
        ((float4*)q2s)[t - 128] = ((const float4*)(g_q2 + (size_t)b * D))[t - 128];
    }
    __syncthreads();

    {
        float p = xs[t] * g_u[t] + xs[t + 256] * g_u[t + 256];
#pragma unroll
        for (int o = 16; o; o >>= 1) p += __shfl_xor_sync(0xffffffffu, p, o);
        if (lane == 0) warp_red[w] = p;
        __syncthreads();
        if (t == 0) {
            float s = 0.f;
#pragma unroll
            for (int i = 0; i < 8; i++) s += warp_red[i];
            qb2_sh = s + g_s0;
        }
        __syncthreads();
    }

    const float4* q2s4 = (const float4*)q2s;
    const float* kbase = keys + (size_t)b * KNN * D;
#pragma unroll
    for (int kk = 0; kk < 4; kk++) {
        const int k = w * 4 + kk;
        const float4* kr = (const float4*)(kbase + (size_t)k * D);
        float p = 0.f;
#pragma unroll
        for (int i = 0; i < 4; i++) {
            float4 kv = kr[lane + 32 * i];
            float4 qv = q2s4[lane + 32 * i];
            p += kv.x * qv.x + kv.y * qv.y + kv.z * qv.z + kv.w * qv.w;
        }
#pragma unroll
        for (int o = 16; o; o >>= 1) p += __shfl_xor_sync(0xffffffffu, p, o);
        if (lane == 0) att_s[k] = (p + qb2_sh) * SCORE_SCALE;
    }
    __syncthreads();

    if (t < 32) {
        float s = att_s[t];
        float m = s;
#pragma unroll
        for (int o = 16; o; o >>= 1) m = fmaxf(m, __shfl_xor_sync(0xffffffffu, m, o));
        float e = expf(s - m);
        float sum = e;
#pragma unroll
        for (int o = 16; o; o >>= 1) sum += __shfl_xor_sync(0xffffffffu, sum, o);
        att_s[t] = e / sum;
    }
    __syncthreads();

    const float* vbase = values + (size_t)b * KNN * D;
    float ax = 0.f, ay = 0.f;
#pragma unroll 4
    for (int k = 0; k < KNN; k++) {
        float a = att_s[k];
        float2 v = *(const float2*)(vbase + (size_t)k * D + 2 * t);
        ax += a * v.x;
        ay += a * v.y;
    }
    float2 xv = *(const float2*)&xs[2 * t];
    float2 o;
    o.x = 0.5f * xv.x + 0.5f * ax;
    o.y = 0.5f * xv.y + 0.5f * ay;
    *(float2*)(out + (size_t)b * D + 2 * t) = o;
}

// ============================================================
extern "C" void kernel_launch(void* const* d_in, const int* in_sizes, int n_in,
                              void* d_out, int out_size) {
    const float* x      = (const float*)d_in[0];
    const float* keys   = (const float*)d_in[1];
    const float* values = (const float*)d_in[2];
    const float* w1     = (const float*)d_in[3];
    const float* b1     = (const float*)d_in[4];
    const float* w2     = (const float*)d_in[5];
    const float* b2     = (const float*)d_in[6];
    float* out          = (float*)d_out;

    (void)in_sizes; (void)n_in; (void)out_size;

    cudaFuncSetAttribute(k_gemm_q2_mma, cudaFuncAttributeMaxDynamicSharedMemorySize,
                         GEMM_SMEM);

    k_prep_W<<<dim3(16, 16), 256>>>(w1, w2);
    k_prep_aux<<<32, 256>>>(w1, w2, b1, b2);
    k_split_x<<<(B_ROWS * D) / (256 * 8), 256>>>(x);
    k_gemm_q2_mma<<<dim3(4, 64), 256, GEMM_SMEM>>>();
    k_attention<<<B_ROWS, 256>>>(x, keys, values, out);
}

// round 7
// speedup vs baseline: 1.8074x; 1.0010x over previous
#include <cuda_runtime.h>
#include <cuda_bf16.h>
#include <cstdint>
#include <math.h>

#define B_ROWS 8192
#define KNN    32
#define D      512

// 1/sqrt(512)
#define SCORE_SCALE 0.044194173824159220f

// -------- device scratch (allocation-free) --------
__device__ __align__(16) __nv_bfloat16 g_W_hi[(size_t)D * D];   // [n][d]
__device__ __align__(16) __nv_bfloat16 g_W_lo[(size_t)D * D];   // [n][d]
__device__ __align__(16) __nv_bfloat16 g_x_hi[(size_t)B_ROWS * D];
__device__ __align__(16) __nv_bfloat16 g_x_lo[(size_t)B_ROWS * D];
__device__ float g_c[D];
__device__ float g_u[D];
__device__ float g_s0;
__device__ __align__(16) float g_q2[(size_t)B_ROWS * D];

// ---- PTX helpers ----
__device__ __forceinline__ uint32_t smem_to_u32(const void* p) {
    uint32_t a;
    asm("{ .reg .u64 tmp; cvta.to.shared.u64 tmp, %1; cvt.u32.u64 %0, tmp; }"
        : "=r"(a) : "l"(p));
    return a;
}
__device__ __forceinline__ void mma_bf16_16816(float* d, const uint32_t* a, const uint32_t* b) {
    asm volatile(
        "mma.sync.aligned.m16n8k16.row.col.f32.bf16.bf16.f32 "
        "{%0,%1,%2,%3}, {%4,%5,%6,%7}, {%8,%9}, {%0,%1,%2,%3};"
        : "+f"(d[0]), "+f"(d[1]), "+f"(d[2]), "+f"(d[3])
        : "r"(a[0]), "r"(a[1]), "r"(a[2]), "r"(a[3]), "r"(b[0]), "r"(b[1]));
}
__device__ __forceinline__ void ldsm_x4(uint32_t& r0, uint32_t& r1, uint32_t& r2, uint32_t& r3,
                                        uint32_t addr) {
    asm volatile("ldmatrix.sync.aligned.m8n8.x4.shared.b16 {%0,%1,%2,%3}, [%4];"
                 : "=r"(r0), "=r"(r1), "=r"(r2), "=r"(r3) : "r"(addr));
}
#define CP_ASYNC_16(dst, src) \
    asm volatile("cp.async.cg.shared.global [%0], [%1], 16;" :: "r"(dst), "l"(src))
#define CP_COMMIT() asm volatile("cp.async.commit_group;" ::: "memory")
#define CP_WAIT1()  asm volatile("cp.async.wait_group 1;" ::: "memory")

// ============================================================
// Kernel 1: W[m,n] = sum_e w1[e,m]*w2[e,n] — 32x32 tiles,
// 256 blocks. Epilogue: bf16 split into g_W_hi/g_W_lo [n][m].
// ============================================================
__global__ __launch_bounds__(256) void k_prep_W(const float* __restrict__ w1,
                                                const float* __restrict__ w2) {
    __shared__ __align__(16) float As[32][36];
    __shared__ __align__(16) float Bs[32][36];
    const int t  = threadIdx.x;
    const int tx = t & 31;
    const int ty = t >> 5;
    const int m0 = blockIdx.y * 32;
    const int n0 = blockIdx.x * 32;

    const int lrow = t >> 3;
    const int lcol = (t & 7) * 4;

    float acc[4] = {0.f, 0.f, 0.f, 0.f};

    for (int k0 = 0; k0 < D; k0 += 32) {
        float4 a = *(const float4*)(w1 + (size_t)(k0 + lrow) * D + m0 + lcol);
        float4 b = *(const float4*)(w2 + (size_t)(k0 + lrow) * D + n0 + lcol);
        *(float4*)&As[lrow][lcol] = a;
        *(float4*)&Bs[lrow][lcol] = b;
        __syncthreads();
#pragma unroll
        for (int k = 0; k < 32; k++) {
            const float bv = Bs[k][tx];
#pragma unroll
            for (int i = 0; i < 4; i++) acc[i] += As[k][ty * 4 + i] * bv;
        }
        __syncthreads();
    }

    const int mbase = m0 + ty * 4;
    const int n = n0 + tx;
    __nv_bfloat16 h4[4], l4[4];
#pragma unroll
    for (int i = 0; i < 4; i++) {
        h4[i] = __float2bfloat16_rn(acc[i]);
        l4[i] = __float2bfloat16_rn(acc[i] - __bfloat162float(h4[i]));
    }
    *(uint2*)(g_W_hi + (size_t)n * D + mbase) = *(const uint2*)h4;
    *(uint2*)(g_W_lo + (size_t)n * D + mbase) = *(const uint2*)l4;
}

// ============================================================
// Kernel 2: c[d], u[d], s0 — 32 blocks, 16 threads per d.
// ============================================================
__global__ __launch_bounds__(256) void k_prep_aux(const float* __restrict__ w1,
                                                  const float* __restrict__ w2,
                                                  const float* __restrict__ b1,
                                                  const float* __restrict__ b2) {
    const int tid = threadIdx.x;
    const int dl = tid >> 4;
    const int el = tid & 15;
    const int d = blockIdx.x * 16 + dl;
    float cacc = 0.f, uacc = 0.f;
#pragma unroll 4
    for (int e = el; e < D; e += 16) {
        cacc += b1[e] * w2[(size_t)e * D + d];
        uacc += b2[e] * w1[(size_t)e * D + d];
    }
#pragma unroll
    for (int o = 8; o; o >>= 1) {
        cacc += __shfl_down_sync(0xffffffffu, cacc, o, 16);
        uacc += __shfl_down_sync(0xffffffffu, uacc, o, 16);
    }
    if (el == 0) { g_c[d] = cacc; g_u[d] = uacc; }
    if (blockIdx.x == 0 && tid < 32) {
        float s = 0.f;
        for (int e = tid; e < D; e += 32) s += b1[e] * b2[e];
#pragma unroll
        for (int o = 16; o; o >>= 1) s += __shfl_xor_sync(0xffffffffu, s, o);
        if (tid == 0) g_s0 = s;
    }
}

// ============================================================
// Kernel 2b: split x -> g_x_hi / g_x_lo.
// ============================================================
__global__ __launch_bounds__(256) void k_split_x(const float* __restrict__ x) {
    const size_t base = ((size_t)blockIdx.x * 256 + threadIdx.x) * 8;
    float4 v0 = *(const float4*)(x + base);
    float4 v1 = *(const float4*)(x + base + 4);
    float f[8] = {v0.x, v0.y, v0.z, v0.w, v1.x, v1.y, v1.z, v1.w};
    __nv_bfloat16 hi[8], lo[8];
#pragma unroll
    for (int i = 0; i < 8; i++) {
        hi[i] = __float2bfloat16_rn(f[i]);
        lo[i] = __float2bfloat16_rn(f[i] - __bfloat162float(hi[i]));
    }
    *(uint4*)(g_x_hi + base) = *(const uint4*)hi;
    *(uint4*)(g_x_lo + base) = *(const uint4*)lo;
}

// ============================================================
// Kernel 3: q2 = x@W + c via 3-term split, A-reuse.
// acc += Ah*Bh + Ah*Bl + Al*Bh  over D in BK=64 chunks (8 iters).
// BM=128, BN=256, 256 threads (2m x 4n warps, warp tile 64x64).
// 2-stage cp.async, SW128 swizzle, ldmatrix.x4.
// grid (2, 64) = 128 CTAs = one wave.
// ============================================================
#define BM 128
#define BN 256
#define BK 64
#define OFF_AH 0
#define OFF_AL 16384
#define OFF_BH 32768
#define OFF_BL 65536
#define STAGE  98304               // 96 KB
#define GEMM_SMEM (2 * STAGE)      // 192 KB
#define NKT (D / BK)               // 8

__global__ __launch_bounds__(256, 1) void k_gemm_q2_mma() {
    extern __shared__ char smem[];
    const uint32_t sbase = smem_to_u32(smem);

    const int t    = threadIdx.x;
    const int lane = t & 31;
    const int wid  = t >> 5;       // 0..7
    const int wm   = wid & 1;      // m warp (64 rows)
    const int wn   = wid >> 1;     // n warp (64 cols)
    const int gid  = lane >> 2;
    const int qid  = lane & 3;

    const int n0 = blockIdx.x * BN;
    const int m0 = blockIdx.y * BM;

    // ---- cp.async source/dest setup ----
    // A tiles: 128 rows x 128B; thread t: row=t>>1, units u0..u0+3
    const int arow = t >> 1;
    const int au0  = (t & 1) * 4;
    // B tiles: 256 rows x 128B; thread t: row=t, units 0..7
    const int brow = t;

    const __nv_bfloat16* AgH = g_x_hi + (size_t)(m0 + arow) * D + au0 * 8;
    const __nv_bfloat16* AgL = g_x_lo + (size_t)(m0 + arow) * D + au0 * 8;
    const __nv_bfloat16* BgH = g_W_hi + (size_t)(n0 + brow) * D;
    const __nv_bfloat16* BgL = g_W_lo + (size_t)(n0 + brow) * D;

    uint32_t adstH[4], adstL[4], bdstH[8], bdstL[8];
#pragma unroll
    for (int i = 0; i < 4; i++) {
        const uint32_t sw = ((uint32_t)((au0 + i) ^ (arow & 7))) << 4;
        adstH[i] = sbase + OFF_AH + arow * 128 + sw;
        adstL[i] = sbase + OFF_AL + arow * 128 + sw;
    }
#pragma unroll
    for (int i = 0; i < 8; i++) {
        const uint32_t sw = ((uint32_t)(i ^ (brow & 7))) << 4;
        bdstH[i] = sbase + OFF_BH + brow * 128 + sw;
        bdstL[i] = sbase + OFF_BL + brow * 128 + sw;
    }

    // ---- ldmatrix lane addressing ----
    const int lr   = lane & 7;
    const int half = (lane >> 3) & 1;
    const int kh   = (lane >> 4) & 1;
    int arow_f[4];
#pragma unroll
    for (int mt = 0; mt < 4; mt++) arow_f[mt] = wm * 64 + mt * 16 + half * 8 + lr;
    const int bmtx   = lane >> 3;
    const int bntoff = bmtx >> 1;
    const int bkh    = bmtx & 1;
    int brow_f[4];
#pragma unroll
    for (int p = 0; p < 4; p++) brow_f[p] = wn * 64 + (p * 2 + bntoff) * 8 + lr;

    float acc[4][8][4];
#pragma unroll
    for (int i = 0; i < 4; i++)
#pragma unroll
        for (int j = 0; j < 8; j++)
#pragma unroll
            for (int r = 0; r < 4; r++) acc[i][j][r] = 0.f;

    // ---- prologue: load stages 0, 1 ----
#pragma unroll
    for (int s = 0; s < 2; s++) {
        const uint32_t soff = (uint32_t)(s * STAGE);
        const int ko = s * BK;
#pragma unroll
        for (int i = 0; i < 4; i++) {
            CP_ASYNC_16(adstH[i] + soff, AgH + ko + i * 8);
            CP_ASYNC_16(adstL[i] + soff, AgL + ko + i * 8);
        }
#pragma unroll
        for (int i = 0; i < 8; i++) {
            CP_ASYNC_16(bdstH[i] + soff, BgH + ko + i * 8);
            CP_ASYNC_16(bdstL[i] + soff, BgL + ko + i * 8);
        }
        CP_COMMIT();
    }

    for (int kt = 0; kt < NKT; kt++) {
        CP_WAIT1();
        __syncthreads();

        const uint32_t S   = sbase + (uint32_t)((kt & 1) * STAGE);
        const uint32_t AHs = S + OFF_AH;
        const uint32_t ALs = S + OFF_AL;
        const uint32_t BHs = S + OFF_BH;
        const uint32_t BLs = S + OFF_BL;

        for (int ks = 0; ks < 4; ks++) {
            uint32_t af_hi[4][4], af_lo[4][4];
#pragma unroll
            for (int mt = 0; mt < 4; mt++) {
                const int row = arow_f[mt];
                const uint32_t off = row * 128 + (((uint32_t)((ks * 2 + kh) ^ (row & 7))) << 4);
                ldsm_x4(af_hi[mt][0], af_hi[mt][1], af_hi[mt][2], af_hi[mt][3], AHs + off);
                ldsm_x4(af_lo[mt][0], af_lo[mt][1], af_lo[mt][2], af_lo[mt][3], ALs + off);
            }
            uint32_t bf_hi[8][2], bf_lo[8][2];
#pragma unroll
            for (int p = 0; p < 4; p++) {
                const int row = brow_f[p];
                const uint32_t off = row * 128 + (((uint32_t)((ks * 2 + bkh) ^ (row & 7))) << 4);
                ldsm_x4(bf_hi[p * 2][0], bf_hi[p * 2][1], bf_hi[p * 2 + 1][0], bf_hi[p * 2 + 1][1],
                        BHs + off);
                ldsm_x4(bf_lo[p * 2][0], bf_lo[p * 2][1], bf_lo[p * 2 + 1][0], bf_lo[p * 2 + 1][1],
                        BLs + off);
            }
#pragma unroll
            for (int mt = 0; mt < 4; mt++)
#pragma unroll
                for (int nt = 0; nt < 8; nt++) {
                    mma_bf16_16816(acc[mt][nt], af_hi[mt], bf_hi[nt]);
                    mma_bf16_16816(acc[mt][nt], af_hi[mt], bf_lo[nt]);
                    mma_bf16_16816(acc[mt][nt], af_lo[mt], bf_hi[nt]);
                }
        }
        __syncthreads();

        // load stage kt+2 into buffer (kt&1) — just finished reading it
        if (kt + 2 < NKT) {
            const uint32_t soff = (uint32_t)((kt & 1) * STAGE);
            const int ko = (kt + 2) * BK;
#pragma unroll
            for (int i = 0; i < 4; i++) {
                CP_ASYNC_16(adstH[i] + soff, AgH + ko + i * 8);
                CP_ASYNC_16(adstL[i] + soff, AgL + ko + i * 8);
            }
#pragma unroll
            for (int i = 0; i < 8; i++) {
                CP_ASYNC_16(bdstH[i] + soff, BgH + ko + i * 8);
                CP_ASYNC_16(bdstL[i] + soff, BgL + ko + i * 8);
            }
        }
        CP_COMMIT();
    }

    // ---- epilogue ----
#pragma unroll
    for (int mt = 0; mt < 4; mt++) {
        const int row0 = m0 + wm * 64 + mt * 16 + gid;
#pragma unroll
        for (int nt = 0; nt < 8; nt++) {
            const int col0 = n0 + wn * 64 + nt * 8 + qid * 2;
            const float c0 = g_c[col0], c1 = g_c[col0 + 1];
            float2 v0 = make_float2(acc[mt][nt][0] + c0, acc[mt][nt][1] + c1);
            float2 v1 = make_float2(acc[mt][nt][2] + c0, acc[mt][nt][3] + c1);
            *(float2*)(g_q2 + (size_t)row0 * D + col0)       = v0;
            *(float2*)(g_q2 + (size_t)(row0 + 8) * D + col0) = v1;
        }
    }
}

// ============================================================
// Kernel 4: per-row attention + blend (DRAM-bound @86%, unchanged)
// ============================================================
__global__ __launch_bounds__(256) void k_attention(const float* __restrict__ x,
                                                   const float* __restrict__ keys,
                                                   const float* __restrict__ values,
                                                   float* __restrict__ out) {
    __shared__ __align__(16) float xs[D];
    __shared__ __align__(16) float q2s[D];
    __shared__ float att_s[KNN];
    __shared__ float warp_red[8];
    __shared__ float qb2_sh;

    const int b    = blockIdx.x;
    const int t    = threadIdx.x;
    const int lane = t & 31;
    const int w    = t >> 5;

    if (t < 128) {
        ((float4*)xs)[t] = ((const float4*)(x + (size_t)b * D))[t];
    } else {
        ((float4*)q2s)[t - 128] = ((const float4*)(g_q2 + (size_t)b * D))[t - 128];
    }
    __syncthreads();

    {
        float p = xs[t] * g_u[t] + xs[t + 256] * g_u[t + 256];
#pragma unroll
        for (int o = 16; o; o >>= 1) p += __shfl_xor_sync(0xffffffffu, p, o);
        if (lane == 0) warp_red[w] = p;
        __syncthreads();
        if (t == 0) {
            float s = 0.f;
#pragma unroll
            for (int i = 0; i < 8; i++) s += warp_red[i];
            qb2_sh = s + g_s0;
        }
        __syncthreads();
    }

    const float4* q2s4 = (const float4*)q2s;
    const float* kbase = keys + (size_t)b * KNN * D;
#pragma unroll
    for (int kk = 0; kk < 4; kk++) {
        const int k = w * 4 + kk;
        const float4* kr = (const float4*)(kbase + (size_t)k * D);
        float p = 0.f;
#pragma unroll
        for (int i = 0; i < 4; i++) {
            float4 kv = kr[lane + 32 * i];
            float4 qv = q2s4[lane + 32 * i];
            p += kv.x * qv.x + kv.y * qv.y + kv.z * qv.z + kv.w * qv.w;
        }
#pragma unroll
        for (int o = 16; o; o >>= 1) p += __shfl_xor_sync(0xffffffffu, p, o);
        if (lane == 0) att_s[k] = (p + qb2_sh) * SCORE_SCALE;
    }
    __syncthreads();

    if (t < 32) {
        float s = att_s[t];
        float m = s;
#pragma unroll
        for (int o = 16; o; o >>= 1) m = fmaxf(m, __shfl_xor_sync(0xffffffffu, m, o));
        float e = expf(s - m);
        float sum = e;
#pragma unroll
        for (int o = 16; o; o >>= 1) sum += __shfl_xor_sync(0xffffffffu, sum, o);
        att_s[t] = e / sum;
    }
    __syncthreads();

    const float* vbase = values + (size_t)b * KNN * D;
    float ax = 0.f, ay = 0.f;
#pragma unroll 4
    for (int k = 0; k < KNN; k++) {
        float a = att_s[k];
        float2 v = *(const float2*)(vbase + (size_t)k * D + 2 * t);
        ax += a * v.x;
        ay += a * v.y;
    }
    float2 xv = *(const float2*)&xs[2 * t];
    float2 o;
    o.x = 0.5f * xv.x + 0.5f * ax;
    o.y = 0.5f * xv.y + 0.5f * ay;
    *(float2*)(out + (size_t)b * D + 2 * t) = o;
}

// ============================================================
extern "C" void kernel_launch(void* const* d_in, const int* in_sizes, int n_in,
                              void* d_out, int out_size) {
    const float* x      = (const float*)d_in[0];
    const float* keys   = (const float*)d_in[1];
    const float* values = (const float*)d_in[2];
    const float* w1     = (const float*)d_in[3];
    const float* b1     = (const float*)d_in[4];
    const float* w2     = (const float*)d_in[5];
    const float* b2     = (const float*)d_in[6];
    float* out          = (float*)d_out;

    (void)in_sizes; (void)n_in; (void)out_size;

    cudaFuncSetAttribute(k_gemm_q2_mma, cudaFuncAttributeMaxDynamicSharedMemorySize,
                         GEMM_SMEM);

    k_prep_W<<<dim3(16, 16), 256>>>(w1, w2);
    k_prep_aux<<<32, 256>>>(w1, w2, b1, b2);
    k_split_x<<<(B_ROWS * D) / (256 * 8), 256>>>(x);
    k_gemm_q2_mma<<<dim3(2, 64), 256, GEMM_SMEM>>>();
    k_attention<<<B_ROWS, 256>>>(x, keys, values, out);
}